// round 15
// baseline (speedup 1.0000x reference)
#include <cuda_runtime.h>
#include <math.h>

#define NB 128
#define NT 1024

typedef unsigned long long u64;

// ---------------- device scratch ----------------
__device__ float g_h[1024 * 256];            // carry h (1 MB)
__device__ float g_p[1024 * 8 * 256];        // lin partials [grp*8+r][64 j][256 d]
__device__ float g_ssp[3][1024 * 256];       // shift / scale / proj_x
__device__ u64   g_wp2[8][128 * 256];        // Wp pair-packed [r][(k2/2)*512 + n*2 + (k2&1)]
__device__ u64   g_wo2[128 * 256];           // Wout pair-packed [k2][n]
__device__ int   g_len[16];
__device__ unsigned g_cnt;                   // global barrier counter (prologue only)
__device__ unsigned g_gcnt[16 * 32];         // per-group counters, 128B apart

// ---------------- f32x2 helpers ----------------
__device__ __forceinline__ void fma2(u64& d, u64 a, u64 b) {
    asm("fma.rn.f32x2 %0, %1, %2, %0;" : "+l"(d) : "l"(a), "l"(b));
}
__device__ __forceinline__ float psum(u64 v) {
    float a, b;
    asm("mov.b64 {%0,%1}, %2;" : "=f"(a), "=f"(b) : "l"(v));
    return a + b;
}
__device__ __forceinline__ u64 pk(float lo, float hi) {
    u64 r;
    asm("mov.b64 %0, {%1,%2};" : "=l"(r) : "f"(lo), "f"(hi));
    return r;
}

// ---------------- barriers (monotonic tickets) ----------------
__device__ __forceinline__ void gsync_all() {
    __syncthreads();
    if (threadIdx.x == 0) {
        __threadfence();
        unsigned ticket = atomicAdd(&g_cnt, 1u);
        unsigned target = (ticket | (NB - 1)) + 1;
        unsigned v;
        do {
            asm volatile("ld.acquire.gpu.u32 %0, [%1];" : "=r"(v) : "l"(&g_cnt) : "memory");
        } while (v < target);
    }
    __syncthreads();
}
__device__ __forceinline__ void gsync_grp(int grp) {
    __syncthreads();
    if (threadIdx.x == 0) {
        __threadfence();
        unsigned* ctr = &g_gcnt[grp * 32];
        unsigned ticket = atomicAdd(ctr, 1u);
        unsigned target = (ticket | 7u) + 1;           // group of 8 CTAs
        unsigned v;
        do {
            asm volatile("ld.acquire.gpu.u32 %0, [%1];" : "=r"(v) : "l"(ctr) : "memory");
        } while (v < target);
    }
    __syncthreads();
}

// ---------------- in_proj micro-kernel (runs once); warp = 8 rows x 64 cols ----
__device__ __forceinline__ void gemm_inproj(u64 (&acc)[8][2], const float* __restrict__ sW,
                                            const float* __restrict__ sX, int wm, int wn, int lane) {
#pragma unroll 2
    for (int kk2 = 0; kk2 < 8; kk2++) {
        const int kb = 4 * kk2;
        u64 wp[2][2];
#pragma unroll
        for (int u = 0; u < 2; u++) {
            int n = 64 * wn + 32 * u + lane;
            wp[u][0] = pk(sW[(kb + 0) * 256 + n], sW[(kb + 1) * 256 + n]);
            wp[u][1] = pk(sW[(kb + 2) * 256 + n], sW[(kb + 3) * 256 + n]);
        }
#pragma unroll
        for (int v = 0; v < 8; v++) {
            float4 af = *(const float4*)&sX[(8 * wm + v) * 32 + kb];
            u64 a01 = pk(af.x, af.y), a23 = pk(af.z, af.w);
#pragma unroll
            for (int u = 0; u < 2; u++) {
                fma2(acc[v][u], a01, wp[u][0]);
                fma2(acc[v][u], a23, wp[u][1]);
            }
        }
    }
}

// ---------------- phase A GEMM: warp = 8 rows x 64 cols; half-chunk = 8 k2p (16 k2) ----
// wb layout: [k2p][256][2] u64 (LDS.128 fragment -> (k2, k2+1) at col n)
__device__ __forceinline__ void gemmA_half(u64 (&acc)[8][2], const u64* __restrict__ wb,
                                           const u64* __restrict__ sXu, int hc,
                                           int wm, int wn, int lane) {
#pragma unroll 2
    for (int k2p = 0; k2p < 8; k2p++) {
        const u64* wrow = wb + k2p * 512;
        u64 w0[2], w1[2];
#pragma unroll
        for (int u = 0; u < 2; u++) {
            ulonglong2 ww = *(const ulonglong2*)&wrow[(64 * wn + 32 * u + lane) * 2];
            w0[u] = ww.x; w1[u] = ww.y;
        }
#pragma unroll
        for (int v = 0; v < 8; v++) {
            ulonglong2 aa = *(const ulonglong2*)&sXu[(8 * wm + v) * 128 + hc * 16 + 2 * k2p];
#pragma unroll
            for (int u = 0; u < 2; u++) {
                fma2(acc[v][u], aa.x, w0[u]);
                fma2(acc[v][u], aa.y, w1[u]);
            }
        }
    }
}

// ---------------- phase B out-GEMM: warp = 8 rows x 64 cols x 4-k2 slice (8-way split) ----
__device__ __forceinline__ void gemmB8(u64 (&acc)[8][2], const u64* __restrict__ wb,
                                       const u64* __restrict__ aU, int aOff,
                                       int wn4, int lane, int ws) {
#pragma unroll
    for (int tp = 0; tp < 2; tp++) {
        const int k2l = ws * 4 + 2 * tp;
        u64 wp00 = wb[k2l * 256 + 64 * wn4 + lane];
        u64 wp01 = wb[k2l * 256 + 64 * wn4 + 32 + lane];
        u64 wp10 = wb[(k2l + 1) * 256 + 64 * wn4 + lane];
        u64 wp11 = wb[(k2l + 1) * 256 + 64 * wn4 + 32 + lane];
#pragma unroll
        for (int v = 0; v < 8; v++) {
            ulonglong2 aa = *(const ulonglong2*)&aU[v * 128 + aOff + k2l];
            fma2(acc[v][0], aa.x, wp00);
            fma2(acc[v][1], aa.x, wp01);
            fma2(acc[v][0], aa.y, wp10);
            fma2(acc[v][1], aa.y, wp11);
        }
    }
}

// dynamic smem float layout (time-shared between phases; As4/sRedA persistent-safe):
//  phase A: sW[2]  @0      (16384 = 2 x 4096 u64 weight halves)
//           sXu    @16384  (16384 = 64 rows x 128 k2 u64, h tile)
//           sP4    @32768  (16384 = 16 i4 x 512 u64, LN(p) quad-packed)
//  phase B: bufu[2]@0      (32768 = 2 x 8192 u64 Wout chunks)
//           sH     @32768  (2048), sRedLN @34816 (64), redK @34880 (16384, ends 51264)
//  persistent (above all phase high-water marks):
//           As4    @51264  (4096 = 16 i4 x 64 j u128, A slice)
//           sRedA  @55360  (512)
#define OFF_AS4   51264
#define OFF_REDA  55360
#define SM_FLOATS 55872
#define SMEM_BYTES (SM_FLOATS * 4)

__global__ __launch_bounds__(NT, 1) void k_persist(
    const int*   __restrict__ tokens, const float* __restrict__ A,
    const float* __restrict__ root,   const float* __restrict__ emb,
    const float* __restrict__ Wp,     const float* __restrict__ bp,
    const float* __restrict__ W_in,   const float* __restrict__ b_in,
    const float* __restrict__ Wout,   const float* __restrict__ bout,
    float* __restrict__ out)
{
    extern __shared__ __align__(16) float sm[];
    const int tid = threadIdx.x, lane = tid & 31, w = tid >> 5;
    const int bid = blockIdx.x;
    const int grp = bid >> 3;                 // batch group (16 groups x 8 CTAs)
    const int r   = bid & 7;                  // this CTA's relation / j-chunk id

    // =================== prologue ===================
    {   // zero carry: one float2 per thread (131072 threads x 2 = 262144)
        int i = (bid * NT + tid) * 2;
        *(float2*)&g_h[i] = make_float2(0.f, 0.f);
    }
    if (bid == 0 && tid < 16) {
        int c = 0;
        for (int l = 0; l < 64; l++) c += (tokens[l * 16 + tid] != 0);
        g_len[tid] = c;
    }
    // pack Wp into g_wp2 (paired layout): 262144 u64, 2 per thread
#pragma unroll
    for (int q = 0; q < 2; q++) {
        int idx = (bid * NT + tid) + q * 131072;
        int n = idx & 255, k2 = (idx >> 8) & 127, rr = idx >> 15;
        float lo = __ldg(&Wp[(2 * k2) * 2048 + rr * 256 + n]);
        float hi = __ldg(&Wp[(2 * k2 + 1) * 2048 + rr * 256 + n]);
        g_wp2[rr][(k2 >> 1) * 512 + n * 2 + (k2 & 1)] = pk(lo, hi);
    }
    // pack Wout into g_wo2
    {
        int gid = bid * NT + tid;
        if (gid < 32768) {
            int n = gid & 255, k2 = gid >> 8;
            g_wo2[k2 * 256 + n] = pk(__ldg(&Wout[2 * k2 * 256 + n]),
                                     __ldg(&Wout[(2 * k2 + 1) * 256 + n]));
        }
    }
    // in_proj: 48 tiles (3 slots x 16 m-tiles of 64 rows)
    if (bid < 48) {
        const int y = bid >> 4, m0 = (bid & 15) * 64;
        const int wm = w >> 2, wn = w & 3;
        float* sW = sm; float* sX = sm + 8192;
        u64 acc[8][2];
#pragma unroll
        for (int v = 0; v < 8; v++) { acc[v][0] = 0ull; acc[v][1] = 0ull; }

        float4 wreg[2], xreg;
#pragma unroll
        for (int q = 0; q < 2; q++) {
            int idx = tid + q * NT, kk = idx >> 6, n4 = idx & 63;
            wreg[q] = __ldg((const float4*)&W_in[kk * 768 + y * 256 + 4 * n4]);
        }
        if (tid < 512) {
            int m = tid >> 3, k4 = tid & 7, row = m0 + m;
            int tok = __ldg(&tokens[(row & 63) * 16 + (row >> 6)]);
            xreg = __ldg((const float4*)&emb[tok * 256 + 4 * k4]);
        }
        for (int kc = 0; kc < 8; kc++) {
            __syncthreads();
#pragma unroll
            for (int q = 0; q < 2; q++) {
                int idx = tid + q * NT, kk = idx >> 6, n4 = idx & 63;
                *(float4*)&sW[kk * 256 + 4 * n4] = wreg[q];
            }
            if (tid < 512) { int m = tid >> 3, k4 = tid & 7; *(float4*)&sX[m * 32 + 4 * k4] = xreg; }
            __syncthreads();
            if (kc < 7) {
                int k0 = (kc + 1) * 32;
#pragma unroll
                for (int q = 0; q < 2; q++) {
                    int idx = tid + q * NT, kk = idx >> 6, n4 = idx & 63;
                    wreg[q] = __ldg((const float4*)&W_in[(k0 + kk) * 768 + y * 256 + 4 * n4]);
                }
                if (tid < 512) {
                    int m = tid >> 3, k4 = tid & 7, row = m0 + m;
                    int tok = __ldg(&tokens[(row & 63) * 16 + (row >> 6)]);
                    xreg = __ldg((const float4*)&emb[tok * 256 + k0 + 4 * k4]);
                }
            }
            gemm_inproj(acc, sW, sX, wm, wn, lane);
        }
#pragma unroll
        for (int v = 0; v < 8; v++) {
            int row = m0 + 8 * wm + v;
#pragma unroll
            for (int u = 0; u < 2; u++) {
                int n = 64 * wn + 32 * u + lane;
                g_ssp[y][row * 256 + n] = psum(acc[v][u]) + __ldg(&b_in[y * 256 + n]);
            }
        }
    }
    gsync_all();

    // ---- persistent A slice: As4[i4][j] u128 (16KB, above all phase scratch) ----
    {
        ulonglong2* As4 = (ulonglong2*)(sm + OFF_AS4);
        int i4 = tid >> 6, j = tid & 63;
        float a0 = __ldg(&A[((grp * 64 + 4 * i4 + 0) * 64 + j) * 8 + r]);
        float a1 = __ldg(&A[((grp * 64 + 4 * i4 + 1) * 64 + j) * 8 + r]);
        float a2 = __ldg(&A[((grp * 64 + 4 * i4 + 2) * 64 + j) * 8 + r]);
        float a3 = __ldg(&A[((grp * 64 + 4 * i4 + 3) * 64 + j) * 8 + r]);
        ulonglong2 t; t.x = pk(a0, a1); t.y = pk(a2, a3);
        As4[i4 * 64 + j] = t;
    }

    // =================== 64 recurrent steps (per-group pipeline) ===================
    for (int st = 0; st < 64; st++) {
        // ---------- phase A: p = LN(h @ Wp_r + bp_r) in smem, then r-partial einsum ----------
        {
            const int m0 = grp * 64;
            const int wm = w >> 2, wn = w & 3;
            u64* sW  = (u64*)sm;                           // [2][4096]
            u64* sXu = (u64*)(sm + 16384);                 // [64][128]
            u64* sP4 = (u64*)(sm + 32768);                 // [16][512]
            const ulonglong2* As4 = (const ulonglong2*)(sm + OFF_AS4);
            float* sRedA = sm + OFF_REDA;

            // stage h tile (64 KB): 4096 float4, 4 per thread
            {
                const float4* src = (const float4*)&g_h[m0 * 256];
                float4* dst = (float4*)sXu;
#pragma unroll
                for (int q = 0; q < 4; q++) {
                    int i = tid + q * NT;
                    dst[i] = __ldcg(&src[i]);
                }
            }
            // weight half-chunk 0 prefetch + store (2048 float4, 2 per thread)
            const float4* wsrc = (const float4*)&g_wp2[r][0];
            float4 wreg[2];
#pragma unroll
            for (int q = 0; q < 2; q++) wreg[q] = __ldg(&wsrc[q * NT + tid]);
            {
                float4* d0 = (float4*)sW;
#pragma unroll
                for (int q = 0; q < 2; q++) d0[q * NT + tid] = wreg[q];
            }
            __syncthreads();

            u64 acc[8][2];
#pragma unroll
            for (int v = 0; v < 8; v++) { acc[v][0] = 0ull; acc[v][1] = 0ull; }

            for (int hc = 0; hc < 8; hc++) {
                if (hc < 7) {
#pragma unroll
                    for (int q = 0; q < 2; q++)
                        wreg[q] = __ldg(&wsrc[(hc + 1) * 2048 + q * NT + tid]);
                }
                gemmA_half(acc, sW + (hc & 1) * 4096, sXu, hc, wm, wn, lane);
                if (hc < 7) {
                    float4* dn = (float4*)(sW + ((hc + 1) & 1) * 4096);
#pragma unroll
                    for (int q = 0; q < 2; q++) dn[q * NT + tid] = wreg[q];
                }
                __syncthreads();
            }
            // bias + per-row LayerNorm (row spans 4 wn warps)
            float x[8][2];
            float bpv[2];
#pragma unroll
            for (int u = 0; u < 2; u++) bpv[u] = __ldg(&bp[r * 256 + 64 * wn + 32 * u + lane]);
#pragma unroll
            for (int v = 0; v < 8; v++) {
                float s = 0.f, s2 = 0.f;
#pragma unroll
                for (int u = 0; u < 2; u++) {
                    x[v][u] = psum(acc[v][u]) + bpv[u];
                    s  += x[v][u];
                    s2 += x[v][u] * x[v][u];
                }
#pragma unroll
                for (int o = 16; o > 0; o >>= 1) {
                    s  += __shfl_xor_sync(0xffffffffu, s,  o);
                    s2 += __shfl_xor_sync(0xffffffffu, s2, o);
                }
                if (lane == 0) {
                    sRedA[(8 * wm + v) * 8 + 2 * wn + 0] = s;
                    sRedA[(8 * wm + v) * 8 + 2 * wn + 1] = s2;
                }
            }
            __syncthreads();
#pragma unroll
            for (int v = 0; v < 8; v++) {
                int row = 8 * wm + v;
                float s = 0.f, s2 = 0.f;
#pragma unroll
                for (int q = 0; q < 4; q++) {
                    s  += sRedA[row * 8 + 2 * q + 0];
                    s2 += sRedA[row * 8 + 2 * q + 1];
                }
                float mean = s * (1.0f / 256.0f);
                float var  = s2 * (1.0f / 256.0f) - mean * mean;
                float inv  = rsqrtf(var + 1e-5f);
#pragma unroll
                for (int u = 0; u < 2; u++) x[v][u] = (x[v][u] - mean) * inv;
            }
            // pack LN(p) quads into sP4: [i4][n][2] u64 (warp owns quads 2wm, 2wm+1)
#pragma unroll
            for (int q4 = 0; q4 < 2; q4++) {
                int i4 = 2 * wm + q4;
#pragma unroll
                for (int u = 0; u < 2; u++) {
                    int n = 64 * wn + 32 * u + lane;
                    ulonglong2 t;
                    t.x = pk(x[4 * q4 + 0][u], x[4 * q4 + 1][u]);
                    t.y = pk(x[4 * q4 + 2][u], x[4 * q4 + 3][u]);
                    *(ulonglong2*)&sP4[i4 * 512 + n * 2] = t;
                }
            }
            __syncthreads();

            // r-partial einsum: lin_r[j][d] = sum_i A[i][j] * p[i][d]  (16 i4)
            u64 acc2[8][2];
#pragma unroll
            for (int v = 0; v < 8; v++) { acc2[v][0] = 0ull; acc2[v][1] = 0ull; }
#pragma unroll 2
            for (int i4 = 0; i4 < 16; i4++) {
                u64 w0[2], w1[2];
#pragma unroll
                for (int u = 0; u < 2; u++) {
                    ulonglong2 ww = *(const ulonglong2*)&sP4[i4 * 512 + (64 * wn + 32 * u + lane) * 2];
                    w0[u] = ww.x; w1[u] = ww.y;
                }
#pragma unroll
                for (int v = 0; v < 8; v++) {
                    ulonglong2 aa = As4[i4 * 64 + 8 * wm + v];
#pragma unroll
                    for (int u = 0; u < 2; u++) {
                        fma2(acc2[v][u], aa.x, w0[u]);
                        fma2(acc2[v][u], aa.y, w1[u]);
                    }
                }
            }
            // write 64KB partial
#pragma unroll
            for (int v = 0; v < 8; v++) {
                int j = 8 * wm + v;
#pragma unroll
                for (int u = 0; u < 2; u++) {
                    int n = 64 * wn + 32 * u + lane;
                    g_p[((grp * 8 + r) * 64 + j) * 256 + n] = psum(acc2[v][u]);
                }
            }
        }
        gsync_grp(grp);

        // ---------- phase B: partial sum + shrink + LN + gate + outGEMM + tanh + mask ----------
        {
            const int j0 = r * 8;
            u64*   bufu   = (u64*)sm;                    // [2][8192]
            float* sH     = sm + 32768;                  // [8][256]
            float* sRedLN = sm + 34816;                  // 64
            float* redK   = sm + 34880;                  // [8][2048], ends 51264 (< OFF_AS4)

            // ----- partial reduction + shrink + LN + gate (warp = (row v8, quarter ch4)) -----
            const int v8 = w >> 2, ch4 = w & 3;
            const int gr = grp * 64 + j0 + v8;
            float tv2[2], s = 0.f, s2 = 0.f;
#pragma unroll
            for (int u = 0; u < 2; u++) {
                int n = ch4 * 64 + 32 * u + lane;
                float lin = 0.f;
#pragma unroll
                for (int r8 = 0; r8 < 8; r8++)
                    lin += __ldcg(&g_p[((grp * 8 + r8) * 64 + j0 + v8) * 256 + n]);
                float tv = __ldg(&g_ssp[2][gr * 256 + n]) + lin - tanhf(lin);
                tv2[u] = tv;
                s += tv; s2 += tv * tv;
            }
#pragma unroll
            for (int o = 16; o > 0; o >>= 1) {
                s  += __shfl_xor_sync(0xffffffffu, s,  o);
                s2 += __shfl_xor_sync(0xffffffffu, s2, o);
            }
            if (lane == 0) {
                sRedLN[v8 * 8 + 2 * ch4 + 0] = s;
                sRedLN[v8 * 8 + 2 * ch4 + 1] = s2;
            }
            __syncthreads();
            {
                float ts = 0.f, ts2 = 0.f;
#pragma unroll
                for (int q = 0; q < 4; q++) {
                    ts  += sRedLN[v8 * 8 + 2 * q + 0];
                    ts2 += sRedLN[v8 * 8 + 2 * q + 1];
                }
                float mean = ts * (1.0f / 256.0f);
                float var  = ts2 * (1.0f / 256.0f) - mean * mean;
                float inv  = rsqrtf(var + 1e-5f);
#pragma unroll
                for (int u = 0; u < 2; u++) {
                    int n = ch4 * 64 + 32 * u + lane;
                    float ln = (tv2[u] - mean) * inv;
                    float hv = __ldg(&g_ssp[0][gr * 256 + n]) * ln + __ldg(&g_ssp[1][gr * 256 + n]);
                    sH[v8 * 256 + n] = fmaxf(hv, 0.0f);
                }
            }
            __syncthreads();

            // ----- out GEMM: y = tanh(h @ Wout + bout); 4 chunks of 32 k2, 8-way k-split -----
            const int wn4 = w & 3, ws = w >> 2;
            u64 acc2[8][2];
#pragma unroll
            for (int v = 0; v < 8; v++) { acc2[v][0] = 0ull; acc2[v][1] = 0ull; }
            const float4* wo = (const float4*)g_wo2;
            float4 wreg[4];
#pragma unroll
            for (int q = 0; q < 4; q++) wreg[q] = __ldg(&wo[q * NT + tid]);
            {
                float4* d0 = (float4*)bufu;
#pragma unroll
                for (int q = 0; q < 4; q++) d0[q * NT + tid] = wreg[q];
            }
            __syncthreads();
            for (int kc = 0; kc < 4; kc++) {
                if (kc < 3) {
#pragma unroll
                    for (int q = 0; q < 4; q++)
                        wreg[q] = __ldg(&wo[(kc + 1) * 4096 + q * NT + tid]);
                }
                gemmB8(acc2, bufu + (kc & 1) * 8192, (const u64*)sH, kc * 32, wn4, lane, ws);
                if (kc < 3) {
                    float4* dn = (float4*)(bufu + ((kc + 1) & 1) * 8192);
#pragma unroll
                    for (int q = 0; q < 4; q++) dn[q * NT + tid] = wreg[q];
                }
                __syncthreads();
            }
            // ----- epilogue: 8-way k-split reduce + tanh + mask -----
#pragma unroll
            for (int v = 0; v < 8; v++)
#pragma unroll
                for (int u = 0; u < 2; u++) {
                    int n = 64 * wn4 + 32 * u + lane;
                    redK[ws * 2048 + v * 256 + n] = psum(acc2[v][u]);
                }
            __syncthreads();
            {
                bool mz = ((64 - st) > g_len[grp]);
#pragma unroll
                for (int u = 0; u < 2; u++) {
                    int n = ch4 * 64 + 32 * u + lane;
                    float lin = __ldg(&bout[n]);
#pragma unroll
                    for (int q = 0; q < 8; q++) lin += redK[q * 2048 + v8 * 256 + n];
                    float yv = tanhf(lin);
                    g_h[gr * 256 + n] = mz ? 0.0f : yv;
                }
            }
        }
        gsync_grp(grp);
    }

    // =================== final reduction (group leader CTA) ===================
    if (r == 0 && tid < 256) {
        float sdot = 0.0f;
        for (int i = 0; i < 64; i++)
            sdot += __ldcg(&g_h[(grp * 64 + i) * 256 + tid]) * __ldg(&root[grp * 64 + i]);
        out[grp * 256 + tid] = sdot;
    }
}

extern "C" void kernel_launch(void* const* d_in, const int* in_sizes, int n_in,
                              void* d_out, int out_size) {
    const int*   tokens = (const int*)  d_in[0];
    const float* A      = (const float*)d_in[1];
    const float* root   = (const float*)d_in[2];
    const float* emb    = (const float*)d_in[3];
    const float* Wp     = (const float*)d_in[4];
    const float* bp     = (const float*)d_in[5];
    const float* W_in   = (const float*)d_in[6];
    const float* b_in   = (const float*)d_in[7];
    const float* Wout   = (const float*)d_in[8];
    const float* bout   = (const float*)d_in[9];
    float* out = (float*)d_out;

    cudaFuncSetAttribute(k_persist, cudaFuncAttributeMaxDynamicSharedMemorySize, SMEM_BYTES);
    k_persist<<<NB, NT, SMEM_BYTES>>>(tokens, A, root, emb, Wp, bp, W_in, b_in, Wout, bout, out);
}